// round 15
// baseline (speedup 1.0000x reference)
#include <cuda_runtime.h>
#include <cuda_fp16.h>

typedef unsigned long long u64;

#define NTOK 8192
#define KTOP 4
#define BW   16
#define DD   512
#define ME   64
#define NK   (NTOK*KTOP)        // 32768
#define UROWS 513               // D+1
#define NDTOT (NTOK*DD)         // 4194304
#define INV_NKB (1.0f/((float)NTOK*KTOP*BW))
#define NBLK 32                 // sort blocks (32 x 1024 = NK)
#define NCOL (ME*BW)            // 1024 columns of Wn
#define GSTR 1028               // G smem row stride (words): mult of 4, bank-spread

// ---------------- scratch (static device globals) -----------------------------
__device__ float  g_rinv[ME*BW];
__device__ float  g_wn[(size_t)DD*NCOL];      // normalized W, [d][col], 2MB
__device__ float  g_gram[(size_t)NCOL*NCOL];  // G = Wn^T Wn, 4MB
__device__ int    g_bcnt[NBLK*ME];
__device__ int    g_base[ME+1];
__device__ int    g_plist[NK];
__device__ __half g_pw[(size_t)NK*DD];        // per-(n,k) partial writes, fp16 (33MB)

// ---------------- packed f32x2 helpers (sm_103a) ------------------------------
__device__ __forceinline__ u64 pack2(float x, float y) {
    u64 r; asm("mov.b64 %0, {%1,%2};" : "=l"(r) : "f"(x), "f"(y)); return r;
}
__device__ __forceinline__ void fma2(u64& d, u64 a, u64 b) {
    asm("fma.rn.f32x2 %0, %1, %2, %0;" : "+l"(d) : "l"(a), "l"(b));
}
__device__ __forceinline__ float2 unpack2(u64 v) {
    float2 f; asm("mov.b64 {%0,%1}, %2;" : "=f"(f.x), "=f"(f.y) : "l"(v)); return f;
}
__device__ __forceinline__ unsigned f2h2(float x, float y) {
    __half2 h = __float22half2_rn(make_float2(x, y));
    return *reinterpret_cast<unsigned*>(&h);
}
__device__ __forceinline__ float2 h2f2(unsigned u) {
    __half2 h = *reinterpret_cast<__half2*>(&u);
    return __half22float2(h);
}

// warp-wide match of 6-bit expert id -> mask of lanes with same value
__device__ __forceinline__ unsigned match6(int m) {
    unsigned mask = 0xffffffffu;
    #pragma unroll
    for (int bit = 0; bit < 6; bit++) {
        unsigned bb = __ballot_sync(0xffffffffu, (m >> bit) & 1);
        mask &= ((m >> bit) & 1) ? bb : ~bb;
    }
    return mask;
}

// ---------------- kernel 1: column norms -> rinv + normalized Wn --------------
__global__ __launch_bounds__(256) void k_norm(const float* __restrict__ U) {
    const int m = blockIdx.x, t = threadIdx.x;
    const float* Um = U + (size_t)m * UROWS * BW;
    const int b = t & 15, g = t >> 4;           // g in 0..15
    float s = 0.f;
    for (int d = g; d < UROWS; d += 16) { float v = Um[d*BW + b]; s += v*v; }
    __shared__ float red[256];
    __shared__ float rv[BW];
    red[t] = s; __syncthreads();
    #pragma unroll
    for (int o = 128; o >= 16; o >>= 1) { if (t < o) red[t] += red[t+o]; __syncthreads(); }
    if (t < 16) rv[t] = rsqrtf(red[t]);
    __syncthreads();
    if (t < 16) g_rinv[m*BW + t] = rv[t];
    float rb = rv[b];
    for (int d = g; d < DD; d += 16)            // only d < 512 feeds writes/recon
        g_wn[(size_t)d*NCOL + m*BW + b] = Um[d*BW + b] * rb;
}

// ---------------- kernel 2: per-block expert histogram (atomic-free) ----------
__global__ __launch_bounds__(1024) void k_cnt(const int* __restrict__ idx) {
    const int t = threadIdx.x, blk = blockIdx.x;
    const int w = t >> 5, l = t & 31;
    __shared__ int wh[32][ME];
    ((int*)wh)[t] = 0; ((int*)wh)[t + 1024] = 0;
    __syncthreads();
    int m = idx[blk*1024 + t];
    unsigned mask = match6(m);
    if (l == (__ffs(mask) - 1)) wh[w][m] = __popc(mask);
    __syncthreads();
    if (t < ME) {
        int s2 = 0;
        #pragma unroll
        for (int w2 = 0; w2 < 32; w2++) s2 += wh[w2][t];
        g_bcnt[blk*ME + t] = s2;
    }
}

// ---------------- kernel 3: deterministic placement (stable counting sort) ----
__global__ __launch_bounds__(1024) void k_place(const int* __restrict__ idx) {
    const int t = threadIdx.x, w = t >> 5, l = t & 31;
    const int blk = blockIdx.x;
    __shared__ int wh[32][ME];
    __shared__ int woff[32][ME];
    __shared__ int bb[ME];
    __shared__ int tot[ME];
    ((int*)wh)[t] = 0; ((int*)wh)[t + 1024] = 0;
    __syncthreads();
    const int p = blk*1024 + t;
    const int m = idx[p];
    unsigned mask = match6(m);
    int rank = __popc(mask & ((1u << l) - 1u));
    if (l == (__ffs(mask) - 1)) wh[w][m] = __popc(mask);
    __syncthreads();
    if (t < ME) {
        int pre = 0, total = 0;
        for (int bk = 0; bk < NBLK; bk++) {
            int c = g_bcnt[bk*ME + t];
            if (bk < blk) pre += c;
            total += c;
        }
        tot[t] = total; bb[t] = pre;
        int run = 0;
        #pragma unroll
        for (int w2 = 0; w2 < 32; w2++) { woff[w2][t] = run; run += wh[w2][t]; }
    }
    __syncthreads();
    if (t < ME) {
        int gb = 0;
        for (int m2 = 0; m2 < t; m2++) gb += tot[m2];
        bb[t] += gb;
        if (blk == 0) { g_base[t] = gb; if (t == 0) g_base[ME] = NK; }
    }
    __syncthreads();
    g_plist[bb[m] + woff[w][m] + rank] = p;
}

// ---------------- kernel 4: stage 1 (pw[p][d] = Un[e_p] @ h_p, fp16 out) -----
__global__ __launch_bounds__(128) void k_stage1(const float* __restrict__ hs,
                                                const float* __restrict__ U) {
    const int m = blockIdx.x >> 3, s = blockIdx.x & 7;
    const int t = threadIdx.x;
    __shared__ u64 h2s[BW*64];        // [b][pair], pre-duplicated {h,h}
    __shared__ int list_s[64];
    __shared__ float rv[BW];
    if (t < BW) rv[t] = g_rinv[m*BW + t];
    __syncthreads();

    u64 u01[BW], u23[BW];
    {
        const float* Um = U + (size_t)m*UROWS*BW + (size_t)t*4*BW;
        #pragma unroll
        for (int b4 = 0; b4 < 4; b4++) {
            float4 v0 = *(const float4*)(Um + 0*BW + b4*4);
            float4 v1 = *(const float4*)(Um + 1*BW + b4*4);
            float4 v2 = *(const float4*)(Um + 2*BW + b4*4);
            float4 v3 = *(const float4*)(Um + 3*BW + b4*4);
            const float* p0 = &v0.x; const float* p1 = &v1.x;
            const float* p2 = &v2.x; const float* p3 = &v3.x;
            #pragma unroll
            for (int j = 0; j < 4; j++) {
                int b = b4*4 + j; float rb = rv[b];
                u01[b] = pack2(p0[j]*rb, p1[j]*rb);
                u23[b] = pack2(p2[j]*rb, p3[j]*rb);
            }
        }
    }

    int lo = g_base[m], hi = g_base[m+1], len = hi - lo;
    int j0 = lo + (len * s) / 8, j1 = lo + (len * (s+1)) / 8;

    for (int cb = j0; cb < j1; cb += 64) {
        int cn = min(64, j1 - cb);
        __syncthreads();
        if (t < cn) list_s[t] = g_plist[cb + t];
        __syncthreads();
        if (t < 64) {
            const float4* hp4 = (const float4*)(hs + (size_t)list_s[min(t, cn-1)]*BW);
            #pragma unroll
            for (int g = 0; g < 4; g++) {
                float4 v = hp4[g];
                h2s[(g*4+0)*64 + t] = pack2(v.x, v.x);
                h2s[(g*4+1)*64 + t] = pack2(v.y, v.y);
                h2s[(g*4+2)*64 + t] = pack2(v.z, v.z);
                h2s[(g*4+3)*64 + t] = pack2(v.w, v.w);
            }
        }
        __syncthreads();
        for (int pb = 0; pb < cn; pb += 8) {
            u64 a0[8], a1[8];
            #pragma unroll
            for (int q = 0; q < 8; q++) { a0[q] = 0ull; a1[q] = 0ull; }
            #pragma unroll
            for (int b = 0; b < BW; b++) {
                const u64* hp = &h2s[b*64 + pb];
                #pragma unroll
                for (int q = 0; q < 8; q++) {
                    u64 h2 = hp[q];
                    fma2(a0[q], u01[b], h2);
                    fma2(a1[q], u23[b], h2);
                }
            }
            int qmax = min(8, cn - pb);
            for (int q = 0; q < qmax; q++) {
                int pr = list_s[pb + q];
                float2 x = unpack2(a0[q]), y = unpack2(a1[q]);
                uint2 hv; hv.x = f2h2(x.x, x.y); hv.y = f2h2(y.x, y.y);
                *(uint2*)&g_pw[(size_t)pr*DD + t*4] = hv;
            }
        }
    }
}

// ---------------- kernel 5: writes[n][d] = sum_k pw[n][k][d]; zero loss -------
__global__ void k_reduce(float* __restrict__ out) {
    int e = blockIdx.x * 256 + threadIdx.x;   // over NTOK*64
    int n = e >> 6, dq = e & 63;
    const uint4* base = (const uint4*)(g_pw + (size_t)n * 4 * DD + dq * 8);
    uint4 w0 = __ldcs(base),        w1 = __ldcs(base + DD/8);
    uint4 w2 = __ldcs(base + DD/4), w3 = __ldcs(base + 3*DD/8);
    float acc[8];
    #pragma unroll
    for (int i = 0; i < 8; i++) acc[i] = 0.f;
    const uint4* ws[4] = {&w0, &w1, &w2, &w3};
    #pragma unroll
    for (int r = 0; r < 4; r++) {
        const unsigned* u = (const unsigned*)ws[r];
        #pragma unroll
        for (int g = 0; g < 4; g++) {
            float2 f = h2f2(u[g]);
            acc[g*2+0] += f.x; acc[g*2+1] += f.y;
        }
    }
    float4* o4 = (float4*)(out + (size_t)n * DD + dq * 8);
    o4[0] = make_float4(acc[0], acc[1], acc[2], acc[3]);
    o4[1] = make_float4(acc[4], acc[5], acc[6], acc[7]);
    if (e == 0) out[NDTOT] = 0.f;
}

// ---------------- kernel 6: G = Wn^T Wn (upper-triangle 64x64 tiles) ----------
// grid = 136 (bi<=bj of 16x16 tile grid), block = 256 (16x16, 4x4 per thread).
__global__ __launch_bounds__(256) void k_gram() {
    __shared__ float As[16][64];
    __shared__ float Bs[16][64];
    int rem = blockIdx.x, bi = 0;
    while (rem >= 16 - bi) { rem -= 16 - bi; bi++; }
    const int bj = bi + rem;
    const int t = threadIdx.x, tx = t & 15, ty = t >> 4;

    u64 accL[4], accR[4];
    #pragma unroll
    for (int r = 0; r < 4; r++) { accL[r] = 0ull; accR[r] = 0ull; }

    const int lr = t >> 4, lc = t & 15;         // tile-load coords (row, float4-col)
    for (int k0 = 0; k0 < DD; k0 += 16) {
        __syncthreads();
        *(float4*)&As[lr][lc*4] = *(const float4*)&g_wn[(size_t)(k0+lr)*NCOL + bi*64 + lc*4];
        *(float4*)&Bs[lr][lc*4] = *(const float4*)&g_wn[(size_t)(k0+lr)*NCOL + bj*64 + lc*4];
        __syncthreads();
        #pragma unroll
        for (int kk = 0; kk < 16; kk++) {
            float4 a4 = *(const float4*)&As[kk][tx*4];
            float4 b4 = *(const float4*)&Bs[kk][ty*4];
            u64 bL = pack2(b4.x, b4.y), bR = pack2(b4.z, b4.w);
            const float* ap = &a4.x;
            #pragma unroll
            for (int r = 0; r < 4; r++) {
                u64 ar = pack2(ap[r], ap[r]);
                fma2(accL[r], bL, ar);
                fma2(accR[r], bR, ar);
            }
        }
    }
    #pragma unroll
    for (int r = 0; r < 4; r++) {
        int gi = bi*64 + tx*4 + r;
        int gj = bj*64 + ty*4;
        float2 xl = unpack2(accL[r]), xr = unpack2(accR[r]);
        *(float4*)&g_gram[(size_t)gi*NCOL + gj] = make_float4(xl.x, xl.y, xr.x, xr.y);
        // mirror (G symmetric; values identical -> benign on diagonal blocks)
        g_gram[(size_t)(gj+0)*NCOL + gi] = xl.x;
        g_gram[(size_t)(gj+1)*NCOL + gi] = xl.y;
        g_gram[(size_t)(gj+2)*NCOL + gi] = xr.x;
        g_gram[(size_t)(gj+3)*NCOL + gi] = xr.y;
    }
}

// ---------------- kernel 7: loss via Gram (replaces stage 2) ------------------
// grid = ME (expert e), block = 256. G row-block [16][1024] cached in SMEM.
// recon[p,b] = sum_{k'} G[e*16+b, e'*16+b'] h[n,k',b'];  64 MACs per (p,b).
__global__ __launch_bounds__(256) void k_loss(const float* __restrict__ hs,
                                              const int* __restrict__ idx,
                                              float* __restrict__ out) {
    extern __shared__ float dsm[];
    float* Gs   = dsm;                       // [16][GSTR]
    float* h_s  = dsm + 16*GSTR;             // 16 pairs x 64
    float* lred = h_s + 1024;                // 256
    int*   pl_s = (int*)(lred + 256);        // 16
    int*   idx_s = pl_s + 16;                // 16 x 4
    const int e = blockIdx.x, t = threadIdx.x;
    const int slot = t >> 4, b = t & 15;

    // load G row-block: 16 rows x 1024, padded stride
    for (int i = t; i < 16*256; i += 256) {  // float4 count
        int row = i >> 8, c4 = i & 255;
        *(float4*)&Gs[row*GSTR + c4*4] =
            *(const float4*)&g_gram[(size_t)(e*BW + row)*NCOL + c4*4];
    }
    __syncthreads();

    int lo = g_base[e], hi = g_base[e+1];
    float lloss = 0.f;

    for (int base = lo; base < hi; base += 16) {
        __syncthreads();                      // protect pl_s/h_s/idx_s reuse
        if (t < 16) pl_s[t] = g_plist[min(base + t, hi - 1)];
        __syncthreads();
        {   // stage h rows (16 float4 per pair) and idx rows
            int n = pl_s[slot] >> 2;
            ((float4*)h_s)[slot*16 + b] = ((const float4*)hs)[n*16 + b];
            if (t < 64) idx_s[t] = idx[(pl_s[t >> 2] >> 2)*4 + (t & 3)];
        }
        __syncthreads();
        {
            int p = pl_s[slot];
            u64 acc01 = 0ull, acc23 = 0ull;
            #pragma unroll
            for (int k2 = 0; k2 < 4; k2++) {
                int e2 = idx_s[slot*4 + k2];
                const float4* grow = (const float4*)&Gs[b*GSTR + e2*BW];
                const float4* hrow = (const float4*)&h_s[slot*64 + k2*BW];
                #pragma unroll
                for (int j = 0; j < 4; j++) {
                    float4 g4 = grow[j], h4 = hrow[j];
                    fma2(acc01, pack2(g4.x, g4.y), pack2(h4.x, h4.y));
                    fma2(acc23, pack2(g4.z, g4.w), pack2(h4.z, h4.w));
                }
            }
            float2 xa = unpack2(acc01), xb = unpack2(acc23);
            float v = (xa.x + xa.y) + (xb.x + xb.y);
            float diff = v - h_s[slot*64 + (p & 3)*BW + b];
            if (base + slot < hi) lloss += diff * diff;
        }
    }
    __syncthreads();
    lred[t] = lloss;
    __syncthreads();
    #pragma unroll
    for (int o = 128; o > 0; o >>= 1) { if (t < o) lred[t] += lred[t+o]; __syncthreads(); }
    if (t == 0) atomicAdd(out + NDTOT, lred[0] * INV_NKB);
}

// ---------------- launch ------------------------------------------------------
extern "C" void kernel_launch(void* const* d_in, const int* in_sizes, int n_in,
                              void* d_out, int out_size) {
    const float* hs = nullptr; const int* idx = nullptr; const float* U = nullptr;
    for (int i = 0; i < n_in; i++) {
        if      (in_sizes[i] == NTOK*KTOP*BW) hs  = (const float*)d_in[i];
        else if (in_sizes[i] == NK)           idx = (const int*)d_in[i];
        else if (in_sizes[i] == ME*UROWS*BW)  U   = (const float*)d_in[i];
    }
    float* out = (float*)d_out;

    const int smemL = (16*GSTR + 1024 + 256) * 4 + (16 + 64) * 4;   // ~71KB
    cudaFuncSetAttribute(k_loss, cudaFuncAttributeMaxDynamicSharedMemorySize, smemL);

    k_norm  <<<ME, 256>>>(U);
    k_cnt   <<<NBLK, 1024>>>(idx);
    k_place <<<NBLK, 1024>>>(idx);
    k_stage1<<<ME*8, 128>>>(hs, U);          // launch slot 4 -> ncu target
    k_reduce<<<NTOK*64/256, 256>>>(out);
    k_gram  <<<136, 256>>>();
    k_loss  <<<ME, 256, smemL>>>(hs, idx, out);
}

// round 17
// speedup vs baseline: 1.3728x; 1.3728x over previous
#include <cuda_runtime.h>
#include <cuda_fp16.h>

typedef unsigned long long u64;

#define NTOK 8192
#define KTOP 4
#define BW   16
#define DD   512
#define ME   64
#define NK   (NTOK*KTOP)        // 32768
#define UROWS 513               // D+1
#define NDTOT (NTOK*DD)         // 4194304
#define INV_NKB (1.0f/((float)NTOK*KTOP*BW))
#define NBLK 32                 // sort blocks (32 x 1024 = NK)
#define NCOL (ME*BW)            // 1024 columns of Wn
#define NTILE 16                // 16 x 16 grid of 64-col tiles
#define NTRI  136               // upper-tri tile pairs
#define GSTR 1028               // G smem row stride (words)

// ---------------- scratch (static device globals) -----------------------------
__device__ float  g_rinv[ME*BW];
__device__ float  g_gram[(size_t)NCOL*NCOL];          // G = Wn^T Wn, 4MB
__device__ float  g_gram4[(size_t)4*NTRI*4096];       // K-split partials, 8.9MB
__device__ int    g_bcnt[NBLK*ME];
__device__ int    g_base[ME+1];
__device__ int    g_plist[NK];
__device__ __half g_pw[(size_t)NK*DD];                // fp16 partial writes, 33MB

// ---------------- packed f32x2 helpers (sm_103a) ------------------------------
__device__ __forceinline__ u64 pack2(float x, float y) {
    u64 r; asm("mov.b64 %0, {%1,%2};" : "=l"(r) : "f"(x), "f"(y)); return r;
}
__device__ __forceinline__ void fma2(u64& d, u64 a, u64 b) {
    asm("fma.rn.f32x2 %0, %1, %2, %0;" : "+l"(d) : "l"(a), "l"(b));
}
__device__ __forceinline__ float2 unpack2(u64 v) {
    float2 f; asm("mov.b64 {%0,%1}, %2;" : "=f"(f.x), "=f"(f.y) : "l"(v)); return f;
}
__device__ __forceinline__ unsigned f2h2(float x, float y) {
    __half2 h = __float22half2_rn(make_float2(x, y));
    return *reinterpret_cast<unsigned*>(&h);
}
__device__ __forceinline__ float2 h2f2(unsigned u) {
    __half2 h = *reinterpret_cast<__half2*>(&u);
    return __half22float2(h);
}
__device__ __forceinline__ unsigned match6(int m) {
    unsigned mask = 0xffffffffu;
    #pragma unroll
    for (int bit = 0; bit < 6; bit++) {
        unsigned bb = __ballot_sync(0xffffffffu, (m >> bit) & 1);
        mask &= ((m >> bit) & 1) ? bb : ~bb;
    }
    return mask;
}

// ---------------- kernel 1: column norms -> rinv ------------------------------
__global__ __launch_bounds__(256) void k_norm(const float* __restrict__ U) {
    const int m = blockIdx.x, t = threadIdx.x;
    const float* Um = U + (size_t)m * UROWS * BW;
    const int b = t & 15, g = t >> 4;
    float s = 0.f;
    for (int d = g; d < UROWS; d += 16) { float v = Um[d*BW + b]; s += v*v; }
    __shared__ float red[256];
    red[t] = s; __syncthreads();
    #pragma unroll
    for (int o = 128; o >= 16; o >>= 1) { if (t < o) red[t] += red[t+o]; __syncthreads(); }
    if (t < 16) g_rinv[m*BW + t] = rsqrtf(red[t]);
}

// ---------------- kernel 2: per-block expert histogram (atomic-free) ----------
__global__ __launch_bounds__(1024) void k_cnt(const int* __restrict__ idx) {
    const int t = threadIdx.x, blk = blockIdx.x;
    const int w = t >> 5, l = t & 31;
    __shared__ int wh[32][ME];
    ((int*)wh)[t] = 0; ((int*)wh)[t + 1024] = 0;
    __syncthreads();
    int m = idx[blk*1024 + t];
    unsigned mask = match6(m);
    if (l == (__ffs(mask) - 1)) wh[w][m] = __popc(mask);
    __syncthreads();
    if (t < ME) {
        int s2 = 0;
        #pragma unroll
        for (int w2 = 0; w2 < 32; w2++) s2 += wh[w2][t];
        g_bcnt[blk*ME + t] = s2;
    }
}

// ---------------- kernel 3: deterministic placement (stable counting sort) ----
__global__ __launch_bounds__(1024) void k_place(const int* __restrict__ idx) {
    const int t = threadIdx.x, w = t >> 5, l = t & 31;
    const int blk = blockIdx.x;
    __shared__ int wh[32][ME];
    __shared__ int woff[32][ME];
    __shared__ int bb[ME];
    __shared__ int tot[ME];
    ((int*)wh)[t] = 0; ((int*)wh)[t + 1024] = 0;
    __syncthreads();
    const int p = blk*1024 + t;
    const int m = idx[p];
    unsigned mask = match6(m);
    int rank = __popc(mask & ((1u << l) - 1u));
    if (l == (__ffs(mask) - 1)) wh[w][m] = __popc(mask);
    __syncthreads();
    if (t < ME) {
        int pre = 0, total = 0;
        for (int bk = 0; bk < NBLK; bk++) {
            int c = g_bcnt[bk*ME + t];
            if (bk < blk) pre += c;
            total += c;
        }
        tot[t] = total; bb[t] = pre;
        int run = 0;
        #pragma unroll
        for (int w2 = 0; w2 < 32; w2++) { woff[w2][t] = run; run += wh[w2][t]; }
    }
    __syncthreads();
    if (t < ME) {
        int gb = 0;
        for (int m2 = 0; m2 < t; m2++) gb += tot[m2];
        bb[t] += gb;
        if (blk == 0) { g_base[t] = gb; if (t == 0) g_base[ME] = NK; }
    }
    __syncthreads();
    g_plist[bb[m] + woff[w][m] + rank] = p;
}

// ---------------- kernel 4: stage 1 (pw[p][d] = Un[e_p] @ h_p, fp16 out) -----
// grid = ME*8, block = 128. Thread t owns d = 4t..4t+3. U in SMEM (low regs ->
// high occupancy); h2s is [b][pair] so pair operands are LDS broadcasts.
__global__ __launch_bounds__(128) void k_stage1(const float* __restrict__ hs,
                                                const float* __restrict__ U) {
    const int m = blockIdx.x >> 3, s = blockIdx.x & 7;
    const int t = threadIdx.x;
    __shared__ float Us[BW*DD];       // 32KB, [b][d], rinv-scaled
    __shared__ u64   h2s[BW*64];      // 8KB, [b][pair], pre-duplicated {h,h}
    __shared__ int   list_s[64];
    __shared__ float rv[BW];
    if (t < BW) rv[t] = g_rinv[m*BW + t];
    __syncthreads();
    const float4* Um4 = (const float4*)(U + (size_t)m * UROWS * BW);
    for (int q = t; q < DD*BW/4; q += 128) {
        float4 v = Um4[q];
        int d = q >> 2, b0 = (q & 3) * 4;
        Us[(b0+0)*DD + d] = v.x * rv[b0+0];
        Us[(b0+1)*DD + d] = v.y * rv[b0+1];
        Us[(b0+2)*DD + d] = v.z * rv[b0+2];
        Us[(b0+3)*DD + d] = v.w * rv[b0+3];
    }
    int lo = g_base[m], hi = g_base[m+1], len = hi - lo;
    int j0 = lo + (len * s) / 8, j1 = lo + (len * (s+1)) / 8;

    for (int cb = j0; cb < j1; cb += 64) {
        int cn = min(64, j1 - cb);
        __syncthreads();                  // Us (1st iter) / h2s reuse
        if (t < cn) list_s[t] = g_plist[cb + t];
        __syncthreads();
        if (t < 64) {
            const float4* hp4 = (const float4*)(hs + (size_t)list_s[min(t, cn-1)]*BW);
            #pragma unroll
            for (int g = 0; g < 4; g++) {
                float4 v = hp4[g];
                h2s[(g*4+0)*64 + t] = pack2(v.x, v.x);
                h2s[(g*4+1)*64 + t] = pack2(v.y, v.y);
                h2s[(g*4+2)*64 + t] = pack2(v.z, v.z);
                h2s[(g*4+3)*64 + t] = pack2(v.w, v.w);
            }
        }
        __syncthreads();
        for (int pb = 0; pb < cn; pb += 8) {
            u64 a0[8], a1[8];
            #pragma unroll
            for (int q = 0; q < 8; q++) { a0[q] = 0ull; a1[q] = 0ull; }
            #pragma unroll
            for (int b = 0; b < BW; b++) {
                float4 u = *(const float4*)&Us[b*DD + t*4];
                u64 u01 = pack2(u.x, u.y), u23 = pack2(u.z, u.w);
                const u64* hp = &h2s[b*64 + pb];   // warp-uniform -> broadcast
                #pragma unroll
                for (int q = 0; q < 8; q++) {
                    u64 h2 = hp[q];
                    fma2(a0[q], u01, h2);
                    fma2(a1[q], u23, h2);
                }
            }
            int qmax = min(8, cn - pb);
            for (int q = 0; q < qmax; q++) {
                int pr = list_s[pb + q];
                float2 x = unpack2(a0[q]), y = unpack2(a1[q]);
                uint2 hv; hv.x = f2h2(x.x, x.y); hv.y = f2h2(y.x, y.y);
                *(uint2*)&g_pw[(size_t)pr*DD + t*4] = hv;
            }
        }
    }
}

// ---------------- kernel 5: writes[n][d] = sum_k pw[n][k][d]; zero loss -------
__global__ void k_reduce(float* __restrict__ out) {
    int e = blockIdx.x * 256 + threadIdx.x;   // over NTOK*64
    int n = e >> 6, dq = e & 63;
    const uint4* base = (const uint4*)(g_pw + (size_t)n * 4 * DD + dq * 8);
    uint4 w0 = __ldcs(base),        w1 = __ldcs(base + DD/8);
    uint4 w2 = __ldcs(base + DD/4), w3 = __ldcs(base + 3*DD/8);
    float acc[8];
    #pragma unroll
    for (int i = 0; i < 8; i++) acc[i] = 0.f;
    const uint4* ws[4] = {&w0, &w1, &w2, &w3};
    #pragma unroll
    for (int r = 0; r < 4; r++) {
        const unsigned* u = (const unsigned*)ws[r];
        #pragma unroll
        for (int g = 0; g < 4; g++) {
            float2 f = h2f2(u[g]);
            acc[g*2+0] += f.x; acc[g*2+1] += f.y;
        }
    }
    float4* o4 = (float4*)(out + (size_t)n * DD + dq * 8);
    o4[0] = make_float4(acc[0], acc[1], acc[2], acc[3]);
    o4[1] = make_float4(acc[4], acc[5], acc[6], acc[7]);
    if (e == 0) out[NDTOT] = 0.f;
}

// ---------------- kernel 6: Gram partials (64x64 tiles, K-split x4) -----------
// grid = NTRI*4, block = 256 (16x16, 4x4 per thread). Reads U directly.
__global__ __launch_bounds__(256) void k_gram(const float* __restrict__ U) {
    __shared__ float As[16][64];
    __shared__ float Bs[16][64];
    __shared__ float rvA[64], rvB[64];
    const int kc = blockIdx.x & 3, tb = blockIdx.x >> 2;
    int rem = tb, bi = 0;
    while (rem >= NTILE - bi) { rem -= NTILE - bi; bi++; }
    const int bj = bi + rem;
    const int t = threadIdx.x, tx = t & 15, ty = t >> 4;

    if (t < 64)       rvA[t]      = g_rinv[bi*64 + t];
    else if (t < 128) rvB[t - 64] = g_rinv[bj*64 + (t - 64)];
    __syncthreads();

    u64 accL[4], accR[4];
    #pragma unroll
    for (int r = 0; r < 4; r++) { accL[r] = 0ull; accR[r] = 0ull; }

    const int lr = t >> 4, lc = t & 15;     // panel-load coords
    const int mA = bi*4 + (lc >> 2), mB = bj*4 + (lc >> 2);
    const int b4 = (lc & 3) * 4;
    const float4 ra = *(const float4*)&rvA[lc*4];
    const float4 rb = *(const float4*)&rvB[lc*4];

    for (int p = 0; p < 8; p++) {
        const int k0 = kc*128 + p*16;
        __syncthreads();
        {
            float4 va = *(const float4*)(U + ((size_t)mA*UROWS + k0 + lr)*BW + b4);
            float4 vb = *(const float4*)(U + ((size_t)mB*UROWS + k0 + lr)*BW + b4);
            *(float4*)&As[lr][lc*4] = make_float4(va.x*ra.x, va.y*ra.y, va.z*ra.z, va.w*ra.w);
            *(float4*)&Bs[lr][lc*4] = make_float4(vb.x*rb.x, vb.y*rb.y, vb.z*rb.z, vb.w*rb.w);
        }
        __syncthreads();
        #pragma unroll
        for (int kk = 0; kk < 16; kk++) {
            float4 a4 = *(const float4*)&As[kk][tx*4];
            float4 b4v = *(const float4*)&Bs[kk][ty*4];
            u64 bL = pack2(b4v.x, b4v.y), bR = pack2(b4v.z, b4v.w);
            const float* ap = &a4.x;
            #pragma unroll
            for (int r = 0; r < 4; r++) {
                u64 ar = pack2(ap[r], ap[r]);
                fma2(accL[r], bL, ar);
                fma2(accR[r], bR, ar);
            }
        }
    }
    float* slab = g_gram4 + ((size_t)kc*NTRI + tb)*4096;
    #pragma unroll
    for (int r = 0; r < 4; r++) {
        float2 xl = unpack2(accL[r]), xr = unpack2(accR[r]);
        *(float4*)&slab[(tx*4 + r)*64 + ty*4] = make_float4(xl.x, xl.y, xr.x, xr.y);
    }
}

// ---------------- kernel 7: fold K-slabs -> G (+ mirror, via smem transpose) --
__global__ __launch_bounds__(256) void k_gfold() {
    __shared__ float ts[64][65];
    const int tb = blockIdx.x, t = threadIdx.x;
    int rem = tb, bi = 0;
    while (rem >= NTILE - bi) { rem -= NTILE - bi; bi++; }
    const int bj = bi + rem;
    const float* s0 = g_gram4 + (size_t)tb*4096;
    for (int r = 0; r < 16; r++) {
        int el = r*256 + t;
        float v = s0[el] + s0[(size_t)NTRI*4096 + el]
                + s0[(size_t)2*NTRI*4096 + el] + s0[(size_t)3*NTRI*4096 + el];
        ts[el >> 6][el & 63] = v;
    }
    __syncthreads();
    const int j = t & 63, rr4 = t >> 6;
    for (int r = 0; r < 16; r++) {
        int i = r*4 + rr4;
        g_gram[(size_t)(bi*64 + i)*NCOL + bj*64 + j] = ts[i][j];
        g_gram[(size_t)(bj*64 + i)*NCOL + bi*64 + j] = ts[j][i];  // mirror
    }
}

// ---------------- kernel 8: loss via Gram ------------------------------------
// grid = ME*4 (expert x quarter-list), block = 256 (16 slots x 16 b).
__global__ __launch_bounds__(256) void k_loss(const float* __restrict__ hs,
                                              const int* __restrict__ idx,
                                              float* __restrict__ out) {
    extern __shared__ float dsm[];
    float* Gs   = dsm;                       // [16][GSTR]
    float* h_s  = dsm + 16*GSTR;             // 16 pairs x 64
    float* lred = h_s + 1024;                // 256
    int*   pl_s = (int*)(lred + 256);        // 16
    int*   idx_s = pl_s + 16;                // 64
    const int e = blockIdx.x >> 2, s = blockIdx.x & 3;
    const int t = threadIdx.x;
    const int slot = t >> 4, b = t & 15;

    for (int i = t; i < 16*256; i += 256) {
        int row = i >> 8, c4 = i & 255;
        *(float4*)&Gs[row*GSTR + c4*4] =
            *(const float4*)&g_gram[(size_t)(e*BW + row)*NCOL + c4*4];
    }
    __syncthreads();

    int lo = g_base[e], hi = g_base[e+1], len = hi - lo;
    int j0 = lo + (len * s) / 4, j1 = lo + (len * (s+1)) / 4;
    float lloss = 0.f;

    for (int base = j0; base < j1; base += 16) {
        __syncthreads();
        if (t < 16) pl_s[t] = g_plist[min(base + t, j1 - 1)];
        __syncthreads();
        {
            int n = pl_s[slot] >> 2;
            ((float4*)h_s)[slot*16 + b] = ((const float4*)hs)[n*16 + b];
            if (t < 64) idx_s[t] = idx[(pl_s[t >> 2] >> 2)*4 + (t & 3)];
        }
        __syncthreads();
        {
            int p = pl_s[slot];
            u64 acc01 = 0ull, acc23 = 0ull;
            #pragma unroll
            for (int k2 = 0; k2 < 4; k2++) {
                int e2 = idx_s[slot*4 + k2];
                const float4* grow = (const float4*)&Gs[b*GSTR + e2*BW];
                const float4* hrow = (const float4*)&h_s[slot*64 + k2*BW];
                #pragma unroll
                for (int j = 0; j < 4; j++) {
                    float4 g4 = grow[j], h4 = hrow[j];
                    fma2(acc01, pack2(g4.x, g4.y), pack2(h4.x, h4.y));
                    fma2(acc23, pack2(g4.z, g4.w), pack2(h4.z, h4.w));
                }
            }
            float2 xa = unpack2(acc01), xb = unpack2(acc23);
            float v = (xa.x + xa.y) + (xb.x + xb.y);
            float diff = v - h_s[slot*64 + (p & 3)*BW + b];
            if (base + slot < j1) lloss += diff * diff;
        }
    }
    __syncthreads();
    lred[t] = lloss;
    __syncthreads();
    #pragma unroll
    for (int o = 128; o > 0; o >>= 1) { if (t < o) lred[t] += lred[t+o]; __syncthreads(); }
    if (t == 0) atomicAdd(out + NDTOT, lred[0] * INV_NKB);
}

// ---------------- launch ------------------------------------------------------
extern "C" void kernel_launch(void* const* d_in, const int* in_sizes, int n_in,
                              void* d_out, int out_size) {
    const float* hs = nullptr; const int* idx = nullptr; const float* U = nullptr;
    for (int i = 0; i < n_in; i++) {
        if      (in_sizes[i] == NTOK*KTOP*BW) hs  = (const float*)d_in[i];
        else if (in_sizes[i] == NK)           idx = (const int*)d_in[i];
        else if (in_sizes[i] == ME*UROWS*BW)  U   = (const float*)d_in[i];
    }
    float* out = (float*)d_out;

    const int smemL = (16*GSTR + 1024 + 256) * 4 + (16 + 64) * 4;   // ~71KB
    cudaFuncSetAttribute(k_loss, cudaFuncAttributeMaxDynamicSharedMemorySize, smemL);

    k_norm  <<<ME, 256>>>(U);
    k_cnt   <<<NBLK, 1024>>>(idx);
    k_place <<<NBLK, 1024>>>(idx);
    k_stage1<<<ME*8, 128>>>(hs, U);
    k_reduce<<<NTOK*64/256, 256>>>(out);
    k_gram  <<<NTRI*4, 256>>>(U);
    k_gfold <<<NTRI, 256>>>();
    k_loss  <<<ME*4, 256, smemL>>>(hs, idx, out);
}